// round 3
// baseline (speedup 1.0000x reference)
#include <cuda_runtime.h>

#define THREADS   256
#define M         14          // batch rows per CTA
#define DIMV      128         // DATA + AUG
#define WIDTHV    256
#define DATAV     64
#define BATCH     2048
#define TSTEPS    128
#define SUBSTEPS  4
#define MD        (M*DIMV)    // 1792
#define MW        (M*WIDTHV)  // 3584

// ---------------------------------------------------------------------------
// Fused layer: out[m][j] = act( sum_k in[m][k] * W[j][k] + b[j] )
// 256 threads, thread j owns output column j. Weights streamed via __ldg
// (L2-resident, 512KB shared by all CTAs); activations broadcast from SMEM.
// ---------------------------------------------------------------------------
template<int KDIM, bool RELU>
__device__ __forceinline__ void layer_nxw(const float* __restrict__ in_sm,
                                          float* __restrict__ out_sm,
                                          const float* __restrict__ W,
                                          const float* __restrict__ B,
                                          int j)
{
    const float4* wrow = reinterpret_cast<const float4*>(W + j * KDIM);
    float bj = __ldg(B + j);
    float acc[M];
#pragma unroll
    for (int m = 0; m < M; ++m) acc[m] = bj;

#pragma unroll 2
    for (int k4 = 0; k4 < KDIM / 4; ++k4) {
        float4 w = __ldg(wrow + k4);
#pragma unroll
        for (int m = 0; m < M; ++m) {
            float4 v = *reinterpret_cast<const float4*>(in_sm + m * KDIM + 4 * k4);
            acc[m] = fmaf(w.x, v.x, acc[m]);
            acc[m] = fmaf(w.y, v.y, acc[m]);
            acc[m] = fmaf(w.z, v.z, acc[m]);
            acc[m] = fmaf(w.w, v.w, acc[m]);
        }
    }
#pragma unroll
    for (int m = 0; m < M; ++m) {
        float v = acc[m];
        if (RELU) v = fmaxf(v, 0.0f);
        out_sm[m * WIDTHV + j] = v;
    }
}

// ---------------------------------------------------------------------------
// Output layer: N=128 columns, K=256. Split-K across two thread halves so all
// 256 threads stay busy; half 1 dumps partials into red, half 0 reduces.
// ---------------------------------------------------------------------------
__device__ __forceinline__ void layer_out(const float* __restrict__ h2,
                                          float* __restrict__ outk,
                                          float* __restrict__ red,
                                          const float* __restrict__ W3,
                                          const float* __restrict__ b3,
                                          int tid)
{
    int j    = tid & (DIMV - 1);
    int half = tid >> 7;
    const float4* wrow = reinterpret_cast<const float4*>(W3 + j * WIDTHV + half * (WIDTHV / 2));
    const float*  base = h2 + half * (WIDTHV / 2);

    float acc[M];
#pragma unroll
    for (int m = 0; m < M; ++m) acc[m] = 0.0f;

#pragma unroll 2
    for (int k4 = 0; k4 < (WIDTHV / 2) / 4; ++k4) {
        float4 w = __ldg(wrow + k4);
#pragma unroll
        for (int m = 0; m < M; ++m) {
            float4 v = *reinterpret_cast<const float4*>(base + m * WIDTHV + 4 * k4);
            acc[m] = fmaf(w.x, v.x, acc[m]);
            acc[m] = fmaf(w.y, v.y, acc[m]);
            acc[m] = fmaf(w.z, v.z, acc[m]);
            acc[m] = fmaf(w.w, v.w, acc[m]);
        }
    }

    if (half) {
#pragma unroll
        for (int m = 0; m < M; ++m) red[m * DIMV + j] = acc[m];
    }
    __syncthreads();
    if (!half) {
        float bj = __ldg(b3 + j);
#pragma unroll
        for (int m = 0; m < M; ++m)
            outk[m * DIMV + j] = acc[m] + red[m * DIMV + j] + bj;
    }
    __syncthreads();
}

// f(y) = W3 * relu(W2 * relu(W1*y + b1) + b2) + b3  -> outk
__device__ __forceinline__ void eval_f(const float* __restrict__ in,
                                       float* __restrict__ outk,
                                       float* __restrict__ h1, float* __restrict__ h2,
                                       float* __restrict__ red,
                                       const float* W1, const float* b1,
                                       const float* W2, const float* b2,
                                       const float* W3, const float* b3,
                                       int tid)
{
    layer_nxw<DIMV,  true>(in, h1, W1, b1, tid);
    __syncthreads();
    layer_nxw<WIDTHV, true>(h1, h2, W2, b2, tid);
    __syncthreads();
    layer_out(h2, outk, red, W3, b3, tid);
}

// dst = y + dt * sum_s c[s] * ks[s]   (elementwise over M*DIMV = 7*256 exactly)
template<int NS>
__device__ __forceinline__ void combine(float* __restrict__ dst,
                                        const float* __restrict__ y,
                                        const float* __restrict__ ks,
                                        float dt, const float* c, int tid)
{
#pragma unroll
    for (int r = 0; r < MD / THREADS; ++r) {
        int i = tid + r * THREADS;
        float v = y[i];
#pragma unroll
        for (int s = 0; s < NS; ++s)
            v = fmaf(dt * c[s], ks[s * MD + i], v);
        dst[i] = v;
    }
}

__device__ __forceinline__ void save_state(const float* __restrict__ y,
                                           float* __restrict__ out,
                                           int base, int t, int tid)
{
#pragma unroll
    for (int r = 0; r < (M * DATAV + THREADS - 1) / THREADS; ++r) {
        int i = tid + r * THREADS;
        if (i < M * DATAV) {
            int m = i >> 6, c = i & (DATAV - 1);
            int row = base + m;
            if (row < BATCH)
                out[((size_t)t * BATCH + row) * DATAV + c] = y[m * DIMV + c];
        }
    }
}

extern "C" __global__ void __launch_bounds__(THREADS, 1)
anode_kernel(const float* __restrict__ ts, const float* __restrict__ y0,
             const float* __restrict__ W1, const float* __restrict__ b1,
             const float* __restrict__ W2, const float* __restrict__ b2,
             const float* __restrict__ W3, const float* __restrict__ b3,
             float* __restrict__ out, int out_size)
{
    extern __shared__ float sm[];
    float* tssm = sm;                       // 128
    float* y    = sm + 128;                 // MD
    float* ks   = y    + MD;                // 6*MD
    float* ytmp = ks   + 6 * MD;            // MD
    float* red  = ytmp + MD;                // MD
    float* h1   = red  + MD;                // MW
    float* h2   = h1   + MW;                // MW

    const int tid  = threadIdx.x;
    const int base = blockIdx.x * M;

    if (tid < TSTEPS) tssm[tid] = ts[tid];

    // load batch tile (clamp overhang rows to a valid row; their output is never written)
#pragma unroll
    for (int r = 0; r < MD / THREADS; ++r) {
        int i = tid + r * THREADS;
        int m = i >> 7, c = i & (DIMV - 1);
        int row = base + m; if (row > BATCH - 1) row = BATCH - 1;
        y[i] = y0[row * DIMV + c];
    }
    __syncthreads();

    save_state(y, out, base, 0, tid);

    // Dopri5 tableau
    const float c2[1] = {0.2f};
    const float c3[2] = {3.f/40.f, 9.f/40.f};
    const float c4[3] = {44.f/45.f, -56.f/15.f, 32.f/9.f};
    const float c5[4] = {19372.f/6561.f, -25360.f/2187.f, 64448.f/6561.f, -212.f/729.f};
    const float c6[5] = {9017.f/3168.f, -355.f/33.f, 46732.f/5247.f, 49.f/176.f, -5103.f/18656.f};
    const float cb[6] = {35.f/384.f, 0.f, 500.f/1113.f, 125.f/192.f, -2187.f/6784.f, 11.f/84.f};

#pragma unroll 1
    for (int t = 1; t < TSTEPS; ++t) {
        float dt = (tssm[t] - tssm[t - 1]) * (1.0f / SUBSTEPS);
#pragma unroll 1
        for (int s = 0; s < SUBSTEPS; ++s) {
            eval_f(y,    ks + 0 * MD, h1, h2, red, W1, b1, W2, b2, W3, b3, tid);
            combine<1>(ytmp, y, ks, dt, c2, tid);  __syncthreads();
            eval_f(ytmp, ks + 1 * MD, h1, h2, red, W1, b1, W2, b2, W3, b3, tid);
            combine<2>(ytmp, y, ks, dt, c3, tid);  __syncthreads();
            eval_f(ytmp, ks + 2 * MD, h1, h2, red, W1, b1, W2, b2, W3, b3, tid);
            combine<3>(ytmp, y, ks, dt, c4, tid);  __syncthreads();
            eval_f(ytmp, ks + 3 * MD, h1, h2, red, W1, b1, W2, b2, W3, b3, tid);
            combine<4>(ytmp, y, ks, dt, c5, tid);  __syncthreads();
            eval_f(ytmp, ks + 4 * MD, h1, h2, red, W1, b1, W2, b2, W3, b3, tid);
            combine<5>(ytmp, y, ks, dt, c6, tid);  __syncthreads();
            eval_f(ytmp, ks + 5 * MD, h1, h2, red, W1, b1, W2, b2, W3, b3, tid);
            combine<6>(y, y, ks, dt, cb, tid);     __syncthreads();
        }
        save_state(y, out, base, t, tid);
    }

    // second reference output: num_steps = (T-1)*SUBSTEPS = 508
    if (blockIdx.x == 0 && tid == 0) {
        const long long TOT = (long long)TSTEPS * BATCH * DATAV;
        for (long long i = TOT; i < (long long)out_size; ++i)
            out[i] = 508.0f;
    }
}

extern "C" void kernel_launch(void* const* d_in, const int* in_sizes, int n_in,
                              void* d_out, int out_size)
{
    const float* ts = (const float*)d_in[0];
    const float* y0 = (const float*)d_in[1];
    const float* W1 = (const float*)d_in[2];
    const float* b1 = (const float*)d_in[3];
    const float* W2 = (const float*)d_in[4];
    const float* b2 = (const float*)d_in[5];
    const float* W3 = (const float*)d_in[6];
    const float* b3 = (const float*)d_in[7];
    float* out = (float*)d_out;

    const int smem_bytes = (128 + 9 * MD + 2 * MW) * (int)sizeof(float); // 93,696 B
    cudaFuncSetAttribute(anode_kernel,
                         cudaFuncAttributeMaxDynamicSharedMemorySize, smem_bytes);

    const int grid = (BATCH + M - 1) / M;  // 147 CTAs ~ one per SM
    anode_kernel<<<grid, THREADS, smem_bytes>>>(ts, y0, W1, b1, W2, b2, W3, b3,
                                                out, out_size);
}